// round 1
// baseline (speedup 1.0000x reference)
#include <cuda_runtime.h>
#include <math.h>

#define N_  50000
#define T_  1000
#define KL  5
#define KR  15
#define NC  5
#define TWO_PI_F 6.28318530717958647692f

// ---------------- device scratch (no allocations allowed) ----------------
__device__ float g_cnt[NC];
__device__ float g_samp[4 * NC];
__device__ float g_scos[4 * NC];
__device__ float g_ssin[4 * NC];
__device__ float g_amp_mean[4 * NC];
__device__ float g_ph_mean[4 * NC];
__device__ float g_coef[N_][12];     // off, trend, A0..A3, B0..B3, pad, pad
__device__ float g_sb[4][1024];      // sin(2*pi*f_i * t)
__device__ float g_cb[4][1024];      // cos(2*pi*f_i * t)

// ---------------- kernel 1: zero accumulators ----------------
__global__ void k_zero() {
    int t = threadIdx.x;
    if (t < NC) g_cnt[t] = 0.f;
    if (t < 4 * NC) {
        g_samp[t] = 0.f;
        g_scos[t] = 0.f;
        g_ssin[t] = 0.f;
    }
}

// ---------------- kernel 2: cluster segment sums ----------------
__global__ void k_cluster_reduce(const float* __restrict__ amps,
                                 const float* __restrict__ phs,
                                 const int* __restrict__ labels, int n) {
    __shared__ float s[NC + 3 * 4 * NC];  // cnt[5] | amp[20] | cos[20] | sin[20]
    int tid = threadIdx.x;
    for (int i = tid; i < NC + 60; i += blockDim.x) s[i] = 0.f;
    __syncthreads();

    int idx = blockIdx.x * blockDim.x + tid;
    if (idx < n) {
        int lab = labels[idx];
        atomicAdd(&s[lab], 1.f);
        float4 a = ((const float4*)amps)[idx];
        float4 p = ((const float4*)phs)[idx];
        float av[4] = {a.x, a.y, a.z, a.w};
        float pv[4] = {p.x, p.y, p.z, p.w};
#pragma unroll
        for (int i = 0; i < 4; i++) {
            atomicAdd(&s[NC + i * NC + lab], av[i]);
            float sv, cv;
            sincosf(pv[i], &sv, &cv);
            atomicAdd(&s[NC + 20 + i * NC + lab], cv);
            atomicAdd(&s[NC + 40 + i * NC + lab], sv);
        }
    }
    __syncthreads();
    for (int i = tid; i < NC + 60; i += blockDim.x) {
        float v = s[i];
        if (i < NC)            atomicAdd(&g_cnt[i], v);
        else if (i < NC + 20)  atomicAdd(&g_samp[i - NC], v);
        else if (i < NC + 40)  atomicAdd(&g_scos[i - NC - 20], v);
        else                   atomicAdd(&g_ssin[i - NC - 40], v);
    }
}

// ---------------- kernel 3: cluster means ----------------
__global__ void k_means() {
    int t = threadIdx.x;
    if (t < 4 * NC) {
        int c = t % NC;
        float cnt = g_cnt[c];
        g_amp_mean[t] = g_samp[t] / fmaxf(cnt, 1.f);
        g_ph_mean[t]  = atan2f(g_ssin[t], g_scos[t]);
    }
}

// ---------------- kernel 4: trig basis over time ----------------
__global__ void k_basis(const float* __restrict__ timev) {
    const float freqs[4] = {4.f, 2.f, 1.f, 0.5f};  // 1/period
    int idx = blockIdx.x * blockDim.x + threadIdx.x;
    if (idx < 4 * T_) {
        int i = idx / T_;
        int t = idx % T_;
        float arg = TWO_PI_F * freqs[i] * timev[t];
        float sv, cv;
        sincosf(arg, &sv, &cv);
        g_sb[i][t] = sv;
        g_cb[i][t] = cv;
    }
}

// ---------------- kernel 5: spatial message passing -> coefficients ----------------
__global__ void k_mp(const float* __restrict__ amps, const float* __restrict__ phs,
                     const float* __restrict__ lw, const float* __restrict__ rw,
                     const int* __restrict__ lidx, const int* __restrict__ ridx,
                     const int* __restrict__ labels,
                     const float* __restrict__ coff, const float* __restrict__ ctr) {
    int n = blockIdx.x * blockDim.x + threadIdx.x;
    if (n >= N_) return;

    float4 pa4 = ((const float4*)amps)[n];
    float4 pp4 = ((const float4*)phs)[n];
    float pa[4] = {pa4.x, pa4.y, pa4.z, pa4.w};
    float pp[4] = {pp4.x, pp4.y, pp4.z, pp4.w};

    float la[4] = {0, 0, 0, 0}, lc[4] = {0, 0, 0, 0}, ls[4] = {0, 0, 0, 0};
    float ra[4] = {0, 0, 0, 0}, rc[4] = {0, 0, 0, 0}, rs[4] = {0, 0, 0, 0};

#pragma unroll
    for (int k = 0; k < KL; k++) {
        int j = lidx[n * KL + k];
        float w = lw[n * KL + k];
        float4 a = ((const float4*)amps)[j];
        float4 p = ((const float4*)phs)[j];
        float av[4] = {a.x, a.y, a.z, a.w};
        float pv[4] = {p.x, p.y, p.z, p.w};
#pragma unroll
        for (int i = 0; i < 4; i++) {
            la[i] = fmaf(av[i], w, la[i]);
            float sv, cv;
            sincosf(pv[i], &sv, &cv);
            lc[i] = fmaf(cv, w, lc[i]);
            ls[i] = fmaf(sv, w, ls[i]);
        }
    }
#pragma unroll
    for (int k = 0; k < KR; k++) {
        int j = ridx[n * KR + k];
        float w = rw[n * KR + k];
        float4 a = ((const float4*)amps)[j];
        float4 p = ((const float4*)phs)[j];
        float av[4] = {a.x, a.y, a.z, a.w};
        float pv[4] = {p.x, p.y, p.z, p.w};
#pragma unroll
        for (int i = 0; i < 4; i++) {
            ra[i] = fmaf(av[i], w, ra[i]);
            float sv, cv;
            sincosf(pv[i], &sv, &cv);
            rc[i] = fmaf(cv, w, rc[i]);
            rs[i] = fmaf(sv, w, rs[i]);
        }
    }

    int lab = labels[n];
    bool useClu = g_cnt[lab] > 1.f;

    float out[12];
    out[0] = coff[n];
    out[1] = ctr[n];
    out[10] = 0.f;
    out[11] = 0.f;

#pragma unroll
    for (int i = 0; i < 4; i++) {
        // amplitude channel (is_phase = false)
        float amp_lu = la[i];
        float amp_ru = ra[i] * 0.7f;
        float amp_cu = useClu ? g_amp_mean[i * NC + lab] : pa[i];
        float combA = 0.5f * amp_lu + 0.3f * amp_ru + 0.2f * amp_cu;
        float ampf = 0.7f * pa[i] + 0.3f * combA;

        // phase channel (is_phase = true)
        float ph_lu = atan2f(ls[i], lc[i]);
        float ph_ru = atan2f(rs[i], rc[i]);
        float ph_cu = useClu ? g_ph_mean[i * NC + lab] : pp[i];
        float combP = 0.5f * ph_lu + 0.3f * ph_ru + 0.2f * ph_cu;
        float phf = 0.7f * pp[i] + 0.3f * combP;

        float sv, cv;
        sincosf(phf, &sv, &cv);
        out[2 + i] = ampf * cv;  // multiplies sin(w t)
        out[6 + i] = ampf * sv;  // multiplies cos(w t)
    }

    float4* dst = (float4*)g_coef[n];
    dst[0] = make_float4(out[0], out[1], out[2], out[3]);
    dst[1] = make_float4(out[4], out[5], out[6], out[7]);
    dst[2] = make_float4(out[8], out[9], out[10], out[11]);
}

// ---------------- kernel 6: signal generation (the big one) ----------------
// Each thread owns 4 fixed t-columns; trig basis lives in registers across all rows.
__global__ void __launch_bounds__(256) k_gen(const float* __restrict__ timev,
                                             float* __restrict__ out) {
    int tid = threadIdx.x;
    int t0 = tid * 4;
    bool active = (t0 < T_);

    float tvv[4] = {0, 0, 0, 0};
    float sbv[4][4], cbv[4][4];
    if (active) {
        float4 tv = *(const float4*)(timev + t0);
        tvv[0] = tv.x; tvv[1] = tv.y; tvv[2] = tv.z; tvv[3] = tv.w;
#pragma unroll
        for (int i = 0; i < 4; i++) {
            float4 s4 = *(const float4*)(&g_sb[i][t0]);
            float4 c4 = *(const float4*)(&g_cb[i][t0]);
            sbv[i][0] = s4.x; sbv[i][1] = s4.y; sbv[i][2] = s4.z; sbv[i][3] = s4.w;
            cbv[i][0] = c4.x; cbv[i][1] = c4.y; cbv[i][2] = c4.z; cbv[i][3] = c4.w;
        }
    } else {
#pragma unroll
        for (int i = 0; i < 4; i++)
#pragma unroll
            for (int l = 0; l < 4; l++) { sbv[i][l] = 0.f; cbv[i][l] = 0.f; }
    }

    for (int n = blockIdx.x; n < N_; n += gridDim.x) {
        const float4* cf = (const float4*)g_coef[n];
        float4 c0 = __ldg(&cf[0]);  // off, trend, A0, A1
        float4 c1 = __ldg(&cf[1]);  // A2, A3, B0, B1
        float4 c2 = __ldg(&cf[2]);  // B2, B3, -, -
        if (!active) continue;

        float A[4] = {c0.z, c0.w, c1.x, c1.y};
        float B[4] = {c1.z, c1.w, c2.x, c2.y};

        float r[4];
#pragma unroll
        for (int l = 0; l < 4; l++) {
            float acc = fmaf(c0.y, tvv[l], c0.x);
#pragma unroll
            for (int i = 0; i < 4; i++) {
                acc = fmaf(A[i], sbv[i][l], acc);
                acc = fmaf(B[i], cbv[i][l], acc);
            }
            r[l] = acc;
        }
        *(float4*)(out + (size_t)n * T_ + t0) = make_float4(r[0], r[1], r[2], r[3]);
    }
}

// ---------------- launch ----------------
extern "C" void kernel_launch(void* const* d_in, const int* in_sizes, int n_in,
                              void* d_out, int out_size) {
    const float* timev = (const float*)d_in[0];
    const float* coff  = (const float*)d_in[1];
    const float* ctr   = (const float*)d_in[2];
    const float* amps  = (const float*)d_in[3];
    const float* phs   = (const float*)d_in[4];
    const float* lw    = (const float*)d_in[5];
    const float* rw    = (const float*)d_in[6];
    const int*   lidx  = (const int*)d_in[7];
    const int*   ridx  = (const int*)d_in[8];
    const int*   labels= (const int*)d_in[9];
    float* out = (float*)d_out;

    int n = in_sizes[1];  // N = 50000

    k_zero<<<1, 64>>>();
    k_cluster_reduce<<<(n + 255) / 256, 256>>>(amps, phs, labels, n);
    k_means<<<1, 32>>>();
    k_basis<<<(4 * T_ + 255) / 256, 256>>>(timev);
    k_mp<<<(n + 255) / 256, 256>>>(amps, phs, lw, rw, lidx, ridx, labels, coff, ctr);
    k_gen<<<1184, 256>>>(timev, out);
}